// round 1
// baseline (speedup 1.0000x reference)
#include <cuda_runtime.h>

#define BB 4
#define CC 64
#define NN 8192
#define OO 128
#define KK 20

// Scratch (static device allocations — no cudaMalloc anywhere)
__device__ float g_xt[(size_t)BB * NN * CC];   // x transposed: [b][n][c]
__device__ float g_xx[BB * NN];                // squared norms
__device__ int   g_knn[(size_t)BB * NN * KK];  // top-K indices
__device__ float g_W1at[CC * CC];              // [j][c] = W1[c][j],    c<64, j<64
__device__ float g_W1bt[CC * CC];              // [j][c] = W1[c][64+j], c<64
__device__ float g_W2t[2 * CC * OO];           // [c][o] = W2[o][c]

// ---------------------------------------------------------------------------
// Prep: transpose x -> xt[b][n][c], compute squared norms
// ---------------------------------------------------------------------------
__global__ void prep_x_kernel(const float* __restrict__ x) {
    int b = blockIdx.y;
    int n = blockIdx.x * 256 + threadIdx.x;
    const float* xb = x + (size_t)b * CC * NN;
    float* row = g_xt + ((size_t)b * NN + n) * CC;
    float s = 0.f;
#pragma unroll
    for (int c = 0; c < CC; c++) {
        float v = __ldg(&xb[(size_t)c * NN + n]);  // coalesced across lanes
        row[c] = v;
        s += v * v;
    }
    g_xx[b * NN + n] = s;
}

// ---------------------------------------------------------------------------
// Prep: transpose weights. Only W1 rows c<64 are ever needed (softmax over k
// sums to 1, so gate columns c>=64 contribute exactly center).
// ---------------------------------------------------------------------------
__global__ void prep_w_kernel(const float* __restrict__ W1,
                              const float* __restrict__ W2) {
    int t = blockIdx.x * 256 + threadIdx.x;  // 0..32767
    if (t < 128 * 128) {
        int c = t >> 7, j = t & 127;
        float v = W1[t];
        if (c < CC) {
            if (j < CC) g_W1at[j * CC + c] = v;
            else        g_W1bt[(j - CC) * CC + c] = v;
        }
    } else {
        int t2 = t - 128 * 128;
        int o = t2 >> 7, c2 = t2 & 127;
        g_W2t[c2 * OO + o] = W2[t2];
    }
}

// ---------------------------------------------------------------------------
// Top-K insertion (sorted descending in registers). Strict '>' keeps the
// earliest (lowest) index on ties, matching jax.lax.top_k tie-breaking.
// ---------------------------------------------------------------------------
__device__ __forceinline__ void topk_insert(float (&vals)[KK], int (&idxs)[KK],
                                            float v, int j) {
    if (v > vals[KK - 1]) {
        vals[KK - 1] = v;
        idxs[KK - 1] = j;
#pragma unroll
        for (int p = KK - 1; p > 0; --p) {
            if (vals[p] > vals[p - 1]) {
                float tv = vals[p]; vals[p] = vals[p - 1]; vals[p - 1] = tv;
                int   ti = idxs[p]; idxs[p] = idxs[p - 1]; idxs[p - 1] = ti;
            }
        }
    }
}

// ---------------------------------------------------------------------------
// KNN: 1 query per thread, xi in registers, candidate chunk in shared.
// pd = 2*dot - xxi - xxj ; top-20 kept in registers.
// Inner loop per j per warp: 16 broadcast LDS.128 + 64 FFMA -> FFMA-pipe bound.
// ---------------------------------------------------------------------------
__global__ __launch_bounds__(128) void knn_kernel() {
    int b = blockIdx.y;
    int i = blockIdx.x * 128 + threadIdx.x;
    __shared__ __align__(16) float shx[128][CC];  // [j_local][c]
    __shared__ float shxx[128];
    const float* xtb = g_xt + (size_t)b * NN * CC;

    float xi[CC];
#pragma unroll
    for (int c = 0; c < CC; c++) xi[c] = __ldg(&xtb[(size_t)i * CC + c]);
    float xxi = g_xx[b * NN + i];

    float vals[KK]; int idxs[KK];
#pragma unroll
    for (int k = 0; k < KK; k++) { vals[k] = -3.0e38f; idxs[k] = 0; }

    for (int j0 = 0; j0 < NN; j0 += 128) {
        __syncthreads();
        // cooperative coalesced load of 128 candidate rows
#pragma unroll
        for (int r = 0; r < 64; r++) {
            int lin = r * 128 + threadIdx.x;
            int jl = lin >> 6, c = lin & 63;
            shx[jl][c] = __ldg(&xtb[(size_t)(j0 + jl) * CC + c]);
        }
        shxx[threadIdx.x] = g_xx[b * NN + j0 + threadIdx.x];
        __syncthreads();

        for (int jl = 0; jl < 128; jl++) {
            const float4* row = (const float4*)shx[jl];
            float a0 = 0.f, a1 = 0.f, a2 = 0.f, a3 = 0.f;  // 4 ILP chains
#pragma unroll
            for (int q = 0; q < 16; q++) {
                float4 v = row[q];  // broadcast across lanes
                a0 += xi[4 * q + 0] * v.x;
                a1 += xi[4 * q + 1] * v.y;
                a2 += xi[4 * q + 2] * v.z;
                a3 += xi[4 * q + 3] * v.w;
            }
            float d = (a0 + a1) + (a2 + a3);
            float pd = 2.f * d - xxi - shxx[jl];
            topk_insert(vals, idxs, pd, j0 + jl);
        }
    }
    int* op = g_knn + ((size_t)b * NN + i) * KK;
#pragma unroll
    for (int k = 0; k < KK; k++) op[k] = idxs[k];
}

// ---------------------------------------------------------------------------
// Fused MLP: 4 points per 256-thread block; thread (p = tid>>6, c = tid&63)
// owns column c (<64) of point p. h[k][c] = W1a[:,c]·diff_k + base[c];
// softmax over k; g[c] = sum_k diff*gate (c<64) or xi[c-64] (c>=64);
// out = W2 @ g.
// ---------------------------------------------------------------------------
__global__ __launch_bounds__(256) void mlp_kernel(float* __restrict__ out) {
    int b = blockIdx.y;
    int n0 = blockIdx.x * 4;
    int tid = threadIdx.x;
    int p = tid >> 6, c = tid & 63;

    __shared__ __align__(16) float nbrT[4][CC][24];  // diff[j][k], pitch 24 (16B-aligned rows)
    __shared__ float xi_sh[4][CC];
    __shared__ int   idx_sh[4][KK];
    __shared__ float g_sh[4][2 * CC];

    const float* xtb = g_xt + (size_t)b * NN * CC;

    if (tid < 4 * KK) {
        int pp = tid / KK, k = tid % KK;
        idx_sh[pp][k] = g_knn[((size_t)b * NN + n0 + pp) * KK + k];
    }
    xi_sh[p][c] = __ldg(&xtb[(size_t)(n0 + p) * CC + c]);
    __syncthreads();

    // gather neighbors and form diff = xj - xi, stored transposed [c][k]
    for (int pp = 0; pp < 4; pp++) {
        for (int e = tid; e < KK * CC; e += 256) {
            int k = e >> 6, cc = e & 63;
            nbrT[pp][cc][k] =
                __ldg(&xtb[(size_t)idx_sh[pp][k] * CC + cc]) - xi_sh[pp][cc];
        }
    }
    __syncthreads();

    // h[k] for this thread's column c (<64) of point p
    float h[KK];
#pragma unroll
    for (int k = 0; k < KK; k++) h[k] = 0.f;
    float base = 0.f;
#pragma unroll 8
    for (int j = 0; j < CC; j++) {
        float w  = __ldg(&g_W1at[j * CC + c]);          // coalesced, L1-hot
        base    += __ldg(&g_W1bt[j * CC + c]) * xi_sh[p][j];
        const float4* f4 = (const float4*)nbrT[p][j];   // broadcast
#pragma unroll
        for (int q = 0; q < 5; q++) {
            float4 f = f4[q];
            h[4 * q + 0] += f.x * w;
            h[4 * q + 1] += f.y * w;
            h[4 * q + 2] += f.z * w;
            h[4 * q + 3] += f.w * w;
        }
    }

    // softmax over k, then g
    float m = -3.0e38f;
#pragma unroll
    for (int k = 0; k < KK; k++) { h[k] += base; m = fmaxf(m, h[k]); }
    float s = 0.f;
#pragma unroll
    for (int k = 0; k < KK; k++) { h[k] = __expf(h[k] - m); s += h[k]; }
    float inv = 1.f / s;
    float gdiff = 0.f;
#pragma unroll
    for (int k = 0; k < KK; k++) gdiff += nbrT[p][c][k] * h[k];
    g_sh[p][c]      = gdiff * inv;
    g_sh[p][CC + c] = xi_sh[p][c];  // softmax sums to 1 -> center passes through
    __syncthreads();

    // out[o] = sum_c W2[o][c] * g[c] ; 256 threads cover 4 points x 128 outputs
    int o = tid & 127;
    int pb = (tid >> 7) * 2;
    for (int r = 0; r < 2; r++) {
        int pp = pb + r;
        float acc = 0.f;
#pragma unroll 16
        for (int cc = 0; cc < 2 * CC; cc++)
            acc += __ldg(&g_W2t[cc * OO + o]) * g_sh[pp][cc];
        out[(size_t)b * OO * NN + (size_t)o * NN + (n0 + pp)] = acc;
    }
}

// ---------------------------------------------------------------------------
extern "C" void kernel_launch(void* const* d_in, const int* in_sizes, int n_in,
                              void* d_out, int out_size) {
    const float* x  = (const float*)d_in[0];
    const float* W1 = (const float*)d_in[1];
    const float* W2 = (const float*)d_in[2];
    float* out = (float*)d_out;

    prep_x_kernel<<<dim3(NN / 256, BB), 256>>>(x);
    prep_w_kernel<<<128, 256>>>(W1, W2);
    knn_kernel<<<dim3(NN / 128, BB), 128>>>();
    mlp_kernel<<<dim3(NN / 4, BB), 256>>>(out);
}

// round 2
// speedup vs baseline: 1.8999x; 1.8999x over previous
#include <cuda_runtime.h>

#define BB 4
#define CC 64
#define NN 8192
#define OO 128
#define KK 20

typedef unsigned long long u64;

// Scratch (static device allocations — no cudaMalloc anywhere)
__device__ __align__(16) float g_xt[(size_t)BB * NN * CC];   // x transposed: [b][n][c]
__device__ float g_xx[BB * NN];                // squared norms
__device__ int   g_knn[(size_t)BB * NN * KK];  // top-K indices
__device__ float g_W1at[CC * CC];              // [j][c] = W1[c][j],    c<64, j<64
__device__ float g_W1bt[CC * CC];              // [j][c] = W1[c][64+j], c<64
__device__ float g_W2t[2 * CC * OO];           // [c][o] = W2[o][c]

// ---- packed fp32x2 helpers (bit-exact fp32, 2 MACs/issue; ptxas never emits
// ---- FFMA2 from C++, only via PTX fma.rn.f32x2) --------------------------
__device__ __forceinline__ u64 fma2(u64 a, u64 b, u64 c) {
    u64 d; asm("fma.rn.f32x2 %0, %1, %2, %3;" : "=l"(d) : "l"(a), "l"(b), "l"(c));
    return d;
}
__device__ __forceinline__ u64 add2(u64 a, u64 b) {
    u64 d; asm("add.rn.f32x2 %0, %1, %2;" : "=l"(d) : "l"(a), "l"(b));
    return d;
}
__device__ __forceinline__ u64 pack2(float lo, float hi) {
    u64 d; asm("mov.b64 %0, {%1, %2};" : "=l"(d) : "f"(lo), "f"(hi));
    return d;
}
__device__ __forceinline__ void unpack2(float& lo, float& hi, u64 v) {
    asm("mov.b64 {%0, %1}, %2;" : "=f"(lo), "=f"(hi) : "l"(v));
}

// ---------------------------------------------------------------------------
// Prep: transpose x -> xt[b][n][c], compute squared norms
// ---------------------------------------------------------------------------
__global__ void prep_x_kernel(const float* __restrict__ x) {
    int b = blockIdx.y;
    int n = blockIdx.x * 256 + threadIdx.x;
    const float* xb = x + (size_t)b * CC * NN;
    float* row = g_xt + ((size_t)b * NN + n) * CC;
    float s = 0.f;
#pragma unroll
    for (int c = 0; c < CC; c++) {
        float v = __ldg(&xb[(size_t)c * NN + n]);  // coalesced across lanes
        row[c] = v;
        s += v * v;
    }
    g_xx[b * NN + n] = s;
}

// ---------------------------------------------------------------------------
// Prep: transpose weights. Only W1 rows c<64 are ever needed (softmax over k
// sums to 1, so gate columns c>=64 contribute exactly center).
// ---------------------------------------------------------------------------
__global__ void prep_w_kernel(const float* __restrict__ W1,
                              const float* __restrict__ W2) {
    int t = blockIdx.x * 256 + threadIdx.x;  // 0..32767
    if (t < 128 * 128) {
        int c = t >> 7, j = t & 127;
        float v = W1[t];
        if (c < CC) {
            if (j < CC) g_W1at[j * CC + c] = v;
            else        g_W1bt[(j - CC) * CC + c] = v;
        }
    } else {
        int t2 = t - 128 * 128;
        int o = t2 >> 7, c2 = t2 & 127;
        g_W2t[c2 * OO + o] = W2[t2];
    }
}

// ---------------------------------------------------------------------------
// Top-K insertion (sorted descending in registers, static indices only — a
// dynamic register index would spill to local). Strict '>' keeps earliest
// index on ties, matching jax.lax.top_k.
// ---------------------------------------------------------------------------
__device__ __forceinline__ void topk_insert(float (&vals)[KK], int (&idxs)[KK],
                                            float v, int j) {
    vals[KK - 1] = v;
    idxs[KK - 1] = j;
#pragma unroll
    for (int p = KK - 1; p > 0; --p) {
        if (vals[p] > vals[p - 1]) {
            float tv = vals[p]; vals[p] = vals[p - 1]; vals[p - 1] = tv;
            int   ti = idxs[p]; idxs[p] = idxs[p - 1]; idxs[p - 1] = ti;
        }
    }
}

// ---------------------------------------------------------------------------
// KNN: 1 query per thread, xi packed in registers (32 x f32x2), candidate
// chunk in shared. Inner loop per j per warp:
//   16 LDS.128 (broadcast) + 32 FFMA2 + ~8 epilogue  (was 16 LDS + 64 FFMA)
// ---------------------------------------------------------------------------
__global__ __launch_bounds__(128) void knn_kernel() {
    int b = blockIdx.y;
    int i = blockIdx.x * 128 + threadIdx.x;
    __shared__ __align__(16) float shx[128][CC];  // [j_local][c]
    __shared__ float shxx[128];
    const float* xtb = g_xt + (size_t)b * NN * CC;

    // load query row, pack into 32 f32x2 registers
    u64 xi2[32];
    const float4* xir = (const float4*)(xtb + (size_t)i * CC);
#pragma unroll
    for (int q = 0; q < 16; q++) {
        float4 t = __ldg(&xir[q]);
        xi2[2 * q + 0] = pack2(t.x, t.y);
        xi2[2 * q + 1] = pack2(t.z, t.w);
    }
    float xxi = g_xx[b * NN + i];

    float vals[KK]; int idxs[KK];
#pragma unroll
    for (int k = 0; k < KK; k++) { vals[k] = -3.0e38f; idxs[k] = 0; }

    for (int j0 = 0; j0 < NN; j0 += 128) {
        __syncthreads();
        // cooperative vectorized fill: 16 x LDG.128 / STS.128 per thread
        const float4* src = (const float4*)(xtb + (size_t)j0 * CC);
        float4* dst = (float4*)shx;
#pragma unroll
        for (int r = 0; r < 16; r++) {
            int lin = r * 128 + threadIdx.x;
            dst[lin] = __ldg(&src[lin]);
        }
        shxx[threadIdx.x] = g_xx[b * NN + j0 + threadIdx.x];
        __syncthreads();

#pragma unroll 4
        for (int jl = 0; jl < 128; jl++) {
            const ulonglong2* row = (const ulonglong2*)shx[jl];  // broadcast LDS.128
            u64 a0 = 0ull, a1 = 0ull, a2 = 0ull, a3 = 0ull;     // 8 fp32 chains
#pragma unroll
            for (int q = 0; q < 8; q++) {
                ulonglong2 v0 = row[2 * q];
                ulonglong2 v1 = row[2 * q + 1];
                a0 = fma2(xi2[4 * q + 0], v0.x, a0);
                a1 = fma2(xi2[4 * q + 1], v0.y, a1);
                a2 = fma2(xi2[4 * q + 2], v1.x, a2);
                a3 = fma2(xi2[4 * q + 3], v1.y, a3);
            }
            a0 = add2(a0, a1);
            a2 = add2(a2, a3);
            a0 = add2(a0, a2);
            float lo, hi; unpack2(lo, hi, a0);
            float pd = 2.f * (lo + hi) - xxi - shxx[jl];
            if (pd > vals[KK - 1]) topk_insert(vals, idxs, pd, j0 + jl);
        }
    }
    int* op = g_knn + ((size_t)b * NN + i) * KK;
#pragma unroll
    for (int k = 0; k < KK; k++) op[k] = idxs[k];
}

// ---------------------------------------------------------------------------
// Fused MLP: 4 points per 256-thread block; thread (p = tid>>6, c = tid&63)
// owns column c (<64) of point p. h[k][c] = W1a[:,c]·diff_k + base[c];
// softmax over k; g[c] = sum_k diff*gate (c<64) or xi[c-64] (c>=64);
// out = W2 @ g.
// ---------------------------------------------------------------------------
__global__ __launch_bounds__(256) void mlp_kernel(float* __restrict__ out) {
    int b = blockIdx.y;
    int n0 = blockIdx.x * 4;
    int tid = threadIdx.x;
    int p = tid >> 6, c = tid & 63;

    __shared__ __align__(16) float nbrT[4][CC][24];  // diff[j][k], pitch 24
    __shared__ float xi_sh[4][CC];
    __shared__ int   idx_sh[4][KK];
    __shared__ float g_sh[4][2 * CC];

    const float* xtb = g_xt + (size_t)b * NN * CC;

    if (tid < 4 * KK) {
        int pp = tid / KK, k = tid % KK;
        idx_sh[pp][k] = g_knn[((size_t)b * NN + n0 + pp) * KK + k];
    }
    xi_sh[p][c] = __ldg(&xtb[(size_t)(n0 + p) * CC + c]);
    __syncthreads();

    // gather neighbors and form diff = xj - xi, stored transposed [c][k]
    for (int pp = 0; pp < 4; pp++) {
        for (int e = tid; e < KK * CC; e += 256) {
            int k = e >> 6, cc = e & 63;
            nbrT[pp][cc][k] =
                __ldg(&xtb[(size_t)idx_sh[pp][k] * CC + cc]) - xi_sh[pp][cc];
        }
    }
    __syncthreads();

    // h[k] for this thread's column c (<64) of point p
    float h[KK];
#pragma unroll
    for (int k = 0; k < KK; k++) h[k] = 0.f;
    float base = 0.f;
#pragma unroll 8
    for (int j = 0; j < CC; j++) {
        float w  = __ldg(&g_W1at[j * CC + c]);          // coalesced, L1-hot
        base    += __ldg(&g_W1bt[j * CC + c]) * xi_sh[p][j];
        const float4* f4 = (const float4*)nbrT[p][j];   // broadcast
#pragma unroll
        for (int q = 0; q < 5; q++) {
            float4 f = f4[q];
            h[4 * q + 0] += f.x * w;
            h[4 * q + 1] += f.y * w;
            h[4 * q + 2] += f.z * w;
            h[4 * q + 3] += f.w * w;
        }
    }

    // softmax over k, then g
    float m = -3.0e38f;
#pragma unroll
    for (int k = 0; k < KK; k++) { h[k] += base; m = fmaxf(m, h[k]); }
    float s = 0.f;
#pragma unroll
    for (int k = 0; k < KK; k++) { h[k] = __expf(h[k] - m); s += h[k]; }
    float inv = 1.f / s;
    float gdiff = 0.f;
#pragma unroll
    for (int k = 0; k < KK; k++) gdiff += nbrT[p][c][k] * h[k];
    g_sh[p][c]      = gdiff * inv;
    g_sh[p][CC + c] = xi_sh[p][c];  // softmax sums to 1 -> center passes through
    __syncthreads();

    // out[o] = sum_c W2[o][c] * g[c] ; 256 threads cover 4 points x 128 outputs
    int o = tid & 127;
    int pb = (tid >> 7) * 2;
    for (int r = 0; r < 2; r++) {
        int pp = pb + r;
        float acc = 0.f;
#pragma unroll 16
        for (int cc = 0; cc < 2 * CC; cc++)
            acc += __ldg(&g_W2t[cc * OO + o]) * g_sh[pp][cc];
        out[(size_t)b * OO * NN + (size_t)o * NN + (n0 + pp)] = acc;
    }
}

// ---------------------------------------------------------------------------
extern "C" void kernel_launch(void* const* d_in, const int* in_sizes, int n_in,
                              void* d_out, int out_size) {
    const float* x  = (const float*)d_in[0];
    const float* W1 = (const float*)d_in[1];
    const float* W2 = (const float*)d_in[2];
    float* out = (float*)d_out;

    prep_x_kernel<<<dim3(NN / 256, BB), 256>>>(x);
    prep_w_kernel<<<128, 256>>>(W1, W2);
    knn_kernel<<<dim3(NN / 128, BB), 128>>>();
    mlp_kernel<<<dim3(NN / 4, BB), 256>>>(out);
}